// round 5
// baseline (speedup 1.0000x reference)
#include <cuda_runtime.h>
#include <cstdint>

#define MM 2048
#define NODE 64
#define TT 256
#define RB 16
#define NTHREADS 256

// Scratch (no cudaMalloc allowed): transposed weights (k-major) + softplus table
__device__ __align__(16) float WT_g[TT * NODE * NODE];   // 4 MB
__device__ __align__(16) float st_g[TT * NODE];          // 64 KB, st_g[0][:]=1.0 (IN_SCALE)

// ---------------- phase 0a: W[t][j][k] -> WT[t][k][j] ----------------
__global__ void k_transpose_W(const float* __restrict__ W) {
    __shared__ float tile[64][65];
    int t = blockIdx.x;
    const float* Wt = W + (size_t)t * 4096;
    for (int idx = threadIdx.x; idx < 4096; idx += blockDim.x)
        tile[idx >> 6][idx & 63] = Wt[idx];
    __syncthreads();
    float* O = WT_g + (size_t)t * 4096;
    for (int idx = threadIdx.x; idx < 4096; idx += blockDim.x)
        O[idx] = tile[idx & 63][idx >> 6];   // stride-65 rows -> conflict-free
}

// ---------------- phase 0b: softplus table ----------------
__global__ void k_softplus(const float* __restrict__ ne) {
    int idx = blockIdx.x * blockDim.x + threadIdx.x;
    if (idx >= TT * NODE) return;
    int t = idx >> 6;
    int j = idx & 63;
    float v;
    if (t == 0) {
        v = 1.0f;  // IN_SCALE at t=0
    } else {
        float x = ne[j * TT + t];  // noise_embedding layout (1, NODE, T)
        v = fmaxf(x, 0.0f) + log1pf(expf(-fabsf(x)));  // stable softplus
    }
    st_g[idx] = v;
}

__device__ __forceinline__ void cp_async16(uint32_t dst, const void* src) {
    asm volatile("cp.async.cg.shared.global [%0], [%1], 16;\n" :: "r"(dst), "l"(src));
}

// ---------------- main: fused 255-step recurrence ----------------
__global__ void __launch_bounds__(NTHREADS, 1)
k_chain(const float* __restrict__ b,
        const float* __restrict__ eps0,
        const float* __restrict__ eps,
        float* __restrict__ out)
{
    // W double buffer: Wsh[buf][k][jgroup] (float4 over j) — 32 KB
    __shared__ float4 Wsh[2][NODE][NODE / 4];
    // x double buffer: 8 KB
    __shared__ float xs[2][RB][NODE];

    const int tid = threadIdx.x;
    const int r   = tid >> 4;        // 0..15 : row within CTA tile
    const int c   = tid & 15;        // 0..15 : 4-column group
    const int j0  = c << 2;
    const int m   = blockIdx.x * RB + r;

    float* __restrict__ outx = out;
    float* __restrict__ outm = out + (size_t)MM * NODE * TT;
    float* __restrict__ outs = out + 2 * (size_t)MM * NODE * TT;

    const uint32_t wsh_base = (uint32_t)__cvta_generic_to_shared(&Wsh[0][0][0]);

    // Prefetch W[1] into buffer 1 (buffer parity == t&1)
    {
        const char* src = (const char*)(WT_g + 4096);
        uint32_t dstb = wsh_base + 16384u;
        #pragma unroll
        for (int i = 0; i < 4; i++) {
            int f = tid + i * 256;
            cp_async16(dstb + (uint32_t)f * 16u, src + (size_t)f * 16);
        }
        asm volatile("cp.async.commit_group;\n");
    }

    float xreg[8][4], mreg[8][4];   // 8-step output staging (registers)

    // ---- t = 0: x0 = eps0, m0 = 0 ----
    {
        float4 e0 = *(const float4*)(eps0 + (size_t)m * NODE + j0);
        xreg[0][0] = e0.x; xreg[0][1] = e0.y; xreg[0][2] = e0.z; xreg[0][3] = e0.w;
        mreg[0][0] = 0.f;  mreg[0][1] = 0.f;  mreg[0][2] = 0.f;  mreg[0][3] = 0.f;
        *(float4*)&xs[0][r][j0] = e0;
    }

    #pragma unroll 1
    for (int t = 1; t < TT; ++t) {
        const int cur = (t - 1) & 1;
        const int nxt = t & 1;

        // 1) W[t] has landed (only group pending is W[t]).
        asm volatile("cp.async.wait_group 0;\n");
        // 2) Barrier: W[t] visible to ALL threads; every thread has finished
        //    its step t-1 reads of Wsh[(t+1)&1] and xs[cur] writes are visible.
        __syncthreads();
        // 3) NOW it is safe to overwrite the retired W buffer with W[t+1].
        //    This cp.async overlaps with the FFMA block below and is waited
        //    on at the top of iteration t+1.
        if (t + 1 < TT) {
            const char* src = (const char*)(WT_g + (size_t)(t + 1) * 4096);
            uint32_t dstb = wsh_base + (uint32_t)((t + 1) & 1) * 16384u;
            #pragma unroll
            for (int i = 0; i < 4; i++) {
                int f = tid + i * 256;
                cp_async16(dstb + (uint32_t)f * 16u, src + (size_t)f * 16);
            }
            asm volatile("cp.async.commit_group;\n");
        }

        // Issue global loads early (latency hidden under the FFMA block)
        float4 bv = *(const float4*)(b + t * NODE + j0);
        float4 ev = *(const float4*)(eps + ((size_t)(t - 1) * MM + m) * NODE + j0);
        float4 sv = *(const float4*)(st_g + t * NODE + j0);

        float a0 = bv.x, a1 = bv.y, a2 = bv.z, a3 = bv.w;

        const float4* __restrict__ xrow = (const float4*)&xs[cur][r][0];
        const float4* __restrict__ wcol = &Wsh[nxt][0][c];

        #pragma unroll
        for (int k4 = 0; k4 < 16; ++k4) {
            float4 xv = xrow[k4];                  // broadcast LDS.128
            float4 w0 = wcol[(4 * k4 + 0) * 16];   // conflict-free LDS.128
            float4 w1 = wcol[(4 * k4 + 1) * 16];
            float4 w2 = wcol[(4 * k4 + 2) * 16];
            float4 w3 = wcol[(4 * k4 + 3) * 16];
            a0 += xv.x * w0.x; a1 += xv.x * w0.y; a2 += xv.x * w0.z; a3 += xv.x * w0.w;
            a0 += xv.y * w1.x; a1 += xv.y * w1.y; a2 += xv.y * w1.z; a3 += xv.y * w1.w;
            a0 += xv.z * w2.x; a1 += xv.z * w2.y; a2 += xv.z * w2.z; a3 += xv.z * w2.w;
            a0 += xv.w * w3.x; a1 += xv.w * w3.y; a2 += xv.w * w3.z; a3 += xv.w * w3.w;
        }

        float x0 = a0 + sv.x * ev.x;
        float x1 = a1 + sv.y * ev.y;
        float x2 = a2 + sv.z * ev.z;
        float x3 = a3 + sv.w * ev.w;

        const int tl = t & 7;
        mreg[tl][0] = a0; mreg[tl][1] = a1; mreg[tl][2] = a2; mreg[tl][3] = a3;
        xreg[tl][0] = x0; xreg[tl][1] = x1; xreg[tl][2] = x2; xreg[tl][3] = x3;

        *(float4*)&xs[nxt][r][j0] = make_float4(x0, x1, x2, x3);

        // ---- flush every 8 steps: reversed, 32B-aligned float4 pairs ----
        if (tl == 7) {
            const int cch   = t >> 3;            // chunk id, 0..31
            const int obase = 248 - 8 * cch;     // out offset of t = 8c+7 .. 8c
            float sreg[8][4];
            #pragma unroll
            for (int u = 0; u < 8; ++u) {
                float4 s4 = *(const float4*)(st_g + (8 * cch + u) * NODE + j0);
                sreg[u][0] = s4.x; sreg[u][1] = s4.y; sreg[u][2] = s4.z; sreg[u][3] = s4.w;
            }
            #pragma unroll
            for (int i = 0; i < 4; ++i) {
                size_t base = ((size_t)m * NODE + j0 + i) * TT + obase;
                *(float4*)(outx + base)     = make_float4(xreg[7][i], xreg[6][i], xreg[5][i], xreg[4][i]);
                *(float4*)(outx + base + 4) = make_float4(xreg[3][i], xreg[2][i], xreg[1][i], xreg[0][i]);
                *(float4*)(outm + base)     = make_float4(mreg[7][i], mreg[6][i], mreg[5][i], mreg[4][i]);
                *(float4*)(outm + base + 4) = make_float4(mreg[3][i], mreg[2][i], mreg[1][i], mreg[0][i]);
                *(float4*)(outs + base)     = make_float4(sreg[7][i], sreg[6][i], sreg[5][i], sreg[4][i]);
                *(float4*)(outs + base + 4) = make_float4(sreg[3][i], sreg[2][i], sreg[1][i], sreg[0][i]);
            }
        }
    }
}

extern "C" void kernel_launch(void* const* d_in, const int* in_sizes, int n_in,
                              void* d_out, int out_size) {
    const float* W    = (const float*)d_in[0];   // (T, NODE, NODE)
    const float* b    = (const float*)d_in[1];   // (T, NODE)
    const float* ne   = (const float*)d_in[2];   // (1, NODE, T)
    const float* eps0 = (const float*)d_in[3];   // (M, NODE)
    const float* eps  = (const float*)d_in[4];   // (T-1, M, NODE)
    float* out = (float*)d_out;                  // [x | m | s], each (M, NODE, T)

    k_transpose_W<<<TT, 256>>>(W);
    k_softplus<<<(TT * NODE + 255) / 256, 256>>>(ne);
    k_chain<<<MM / RB, NTHREADS>>>(b, eps0, eps, out);
}